// round 11
// baseline (speedup 1.0000x reference)
#include <cuda_runtime.h>
#include <cuda_fp16.h>
#include <math.h>
#include <stdint.h>

#define NH 8
#define NT 2048
#define NE 512
#define NHT (NH * NT)
#define SPLITK 8
#define KSPLIT (NHT / SPLITK)

typedef __half fp16;

// ---------------- scratch (device globals; no allocation anywhere) ----------------
__device__ __align__(256) fp16 g_xe[(size_t)NT * NE];
__device__ __align__(256) fp16 g_ye[(size_t)NT * NE];
__device__ __align__(256) fp16 g_ze[(size_t)NT * NE];
__device__ __align__(256) fp16 g_Wqe[(size_t)NH * NE * NE];
__device__ __align__(256) fp16 g_Wke[(size_t)NH * NE * NE];
__device__ __align__(256) fp16 g_Wve[(size_t)NH * NE * NE];
__device__ __align__(256) fp16 g_Wfe[(size_t)NT * NHT];
__device__ __align__(256) fp16 g_q[(size_t)NH * NT * NE];    // [h][t][e]
__device__ __align__(256) fp16 g_k[(size_t)NH * NT * NE];    // [h][t][e]
__device__ __align__(256) fp16 g_v[(size_t)NH * NE * NT];    // [h][e][t]  (transposed)
__device__ __align__(256) fp16 g_att[(size_t)NH * NT * NT];  // scores then att (in-place)
__device__ __align__(256) fp16 g_hd[(size_t)NE * NHT];       // heads^T == concat^T [e][h*t]
__device__ __align__(256) float g_part[(size_t)SPLITK * NT * NE];

// ---------------- helpers ----------------
__device__ __forceinline__ uint32_t smem_u32(const void* p) {
    uint32_t a;
    asm("{ .reg .u64 t; cvta.to.shared.u64 t, %1; cvt.u32.u64 %0, t; }" : "=r"(a) : "l"(p));
    return a;
}
__device__ __forceinline__ void cp_async16(uint32_t dst, const void* src) {
    asm volatile("cp.async.cg.shared.global [%0], [%1], 16;" :: "r"(dst), "l"(src));
}
#define CP_COMMIT() asm volatile("cp.async.commit_group;")
#define CP_WAIT1()  asm volatile("cp.async.wait_group 1;")

__device__ __forceinline__ void ldm_x4(uint32_t* r, uint32_t addr) {
    asm volatile("ldmatrix.sync.aligned.m8n8.x4.shared.b16 {%0,%1,%2,%3}, [%4];"
                 : "=r"(r[0]), "=r"(r[1]), "=r"(r[2]), "=r"(r[3]) : "r"(addr));
}
__device__ __forceinline__ void mma16816(float* c, const uint32_t* a, const uint32_t* b) {
    asm volatile(
        "mma.sync.aligned.m16n8k16.row.col.f32.f16.f16.f32 "
        "{%0,%1,%2,%3}, {%4,%5,%6,%7}, {%8,%9}, {%0,%1,%2,%3};"
        : "+f"(c[0]), "+f"(c[1]), "+f"(c[2]), "+f"(c[3])
        : "r"(a[0]), "r"(a[1]), "r"(a[2]), "r"(a[3]), "r"(b[0]), "r"(b[1]));
}
__device__ __forceinline__ uint32_t pack2h(float a, float b) {
    __half2 h = __floats2half2_rn(a, b);
    return *reinterpret_cast<uint32_t*>(&h);
}

// ---------------- fp32 -> fp16 cast (3 tensors per launch) ----------------
__global__ __launch_bounds__(256)
void cast3_kernel(const float* __restrict__ s0, fp16* __restrict__ d0,
                  const float* __restrict__ s1, fp16* __restrict__ d1,
                  const float* __restrict__ s2, fp16* __restrict__ d2, long nq)
{
    const float* src = (blockIdx.y == 0) ? s0 : (blockIdx.y == 1) ? s1 : s2;
    fp16*       dst = (blockIdx.y == 0) ? d0 : (blockIdx.y == 1) ? d1 : d2;
    long i = (long)blockIdx.x * blockDim.x + threadIdx.x;
    const long stride = (long)gridDim.x * blockDim.x;
    for (; i < nq; i += stride) {
        float4 f = reinterpret_cast<const float4*>(src)[i];
        uint2 w;
        w.x = pack2h(f.x, f.y);
        w.y = pack2h(f.z, f.w);
        reinterpret_cast<uint2*>(dst)[i] = w;
    }
}

__global__ __launch_bounds__(256)
void cast_kernel(const float* __restrict__ src, fp16* __restrict__ dst, long nq)
{
    long i = (long)blockIdx.x * blockDim.x + threadIdx.x;
    const long stride = (long)gridDim.x * blockDim.x;
    for (; i < nq; i += stride) {
        float4 f = reinterpret_cast<const float4*>(src)[i];
        uint2 w;
        w.x = pack2h(f.x, f.y);
        w.y = pack2h(f.z, f.w);
        reinterpret_cast<uint2*>(dst)[i] = w;
    }
}

// ---------------- mma.sync fp16 GEMM: 128 threads, warp tile 64x64 ----------------
// C[M=by*128, N=bx*128] = sum_k A[m,k] * B[n,k]   (TN, both row-major fp16, K-contig)
// EPI 0: fp32 out (alpha)
// EPI 1: fp16 out in-row (alpha, +bias_n)   d[(m0+r)*ldW + n0+n]
// EPI 3: fp16 out transposed (+bias_n)      d[(n0+n)*ldW + z*colPerZ + m0+m]
#define BM 128
#define BN 128
#define BKE 64
#define STAGES 3
#define STAGE_BYTES (BM * BKE * 2 + BN * BKE * 2)   // 32768
#define GEMM_SMEM (STAGES * STAGE_BYTES)            // 98304 (x2 CTAs = 196K <= 228K/SM)
#define NTHR 128

template <int EPI>
__global__ __launch_bounds__(NTHR, 2)
void mma_gemm(const fp16* __restrict__ A, const fp16* __restrict__ B, void* Cout,
              int K, long lda, long ldb, long ldW,
              long sA, long sB, long sC, long colPerZ,
              float alpha, const float* __restrict__ bias, long sBias)
{
    extern __shared__ char smem[];
    const int tid = threadIdx.x, lane = tid & 31, wid = tid >> 5;
    const int wm = wid & 1, wn = wid >> 1;       // 2x2 warps, warp tile 64x64
    const int m0 = blockIdx.y * BM, n0 = blockIdx.x * BN, z = blockIdx.z;
    A += (long)z * sA;
    B += (long)z * sB;
    if (bias) bias += (long)z * sBias;
    const uint32_t sbase = smem_u32(smem);

    // each thread loads one full A row and one full B row (8 x 16B chunks each)
    const fp16* Ag = A + (long)(m0 + tid) * lda;
    const fp16* Bg = B + (long)(n0 + tid) * ldb;

    auto aAddr = [&](int s, int r, int c) -> uint32_t {
        return sbase + s * STAGE_BYTES + ((((uint32_t)r << 3) | (uint32_t)(c ^ (r & 7))) << 4);
    };
    auto bAddr = [&](int s, int r, int c) -> uint32_t {
        return sbase + s * STAGE_BYTES + BM * BKE * 2 +
               ((((uint32_t)r << 3) | (uint32_t)(c ^ (r & 7))) << 4);
    };
    auto prefetch = [&](int s, int ch) {
        const fp16* ap = Ag + (long)ch * BKE;
        const fp16* bp = Bg + (long)ch * BKE;
        #pragma unroll
        for (int c = 0; c < 8; c++) {
            cp_async16(aAddr(s, tid, c), ap + c * 8);
            cp_async16(bAddr(s, tid, c), bp + c * 8);
        }
    };

    float acc[4][8][4] = {};     // 4 m16-tiles x 8 n8-tiles x 4 regs = 128 regs
    const int NCH = K / BKE;

    prefetch(0, 0); CP_COMMIT();
    prefetch(1, 1); CP_COMMIT();

    const int a_r  = lane & 15;
    const int a_kc = lane >> 4;
    const int b_r  = (lane & 7) + ((lane >> 4) << 3);
    const int b_kc = (lane >> 3) & 1;

    for (int ch = 0; ch < NCH; ch++) {
        CP_WAIT1();
        __syncthreads();
        if (ch + 2 < NCH) prefetch((ch + 2) % STAGES, ch + 2);
        CP_COMMIT();
        const int s = ch % STAGES;
        #pragma unroll
        for (int ks = 0; ks < 4; ks++) {
            uint32_t a[4][4];
            #pragma unroll
            for (int mt = 0; mt < 4; mt++) {
                int r = wm * 64 + mt * 16 + a_r;
                ldm_x4(a[mt], aAddr(s, r, 2 * ks + a_kc));
            }
            #pragma unroll
            for (int g = 0; g < 4; g++) {
                uint32_t b[4];
                int r = wn * 64 + g * 16 + b_r;
                ldm_x4(b, bAddr(s, r, 2 * ks + b_kc));
                #pragma unroll
                for (int mt = 0; mt < 4; mt++) {
                    mma16816(acc[mt][2 * g],     a[mt], &b[0]);
                    mma16816(acc[mt][2 * g + 1], a[mt], &b[2]);
                }
            }
        }
    }
    __syncthreads();

    // ---- bounce fragments to smem fp32 tile [128][132] ----
    float* S = reinterpret_cast<float*>(smem);
    #pragma unroll
    for (int mt = 0; mt < 4; mt++)
        #pragma unroll
        for (int j = 0; j < 8; j++) {
            int r  = wm * 64 + mt * 16 + (lane >> 2);
            int cc = wn * 64 + j * 8 + (lane & 3) * 2;
            S[r * 132 + cc]           = acc[mt][j][0];
            S[r * 132 + cc + 1]       = acc[mt][j][1];
            S[(r + 8) * 132 + cc]     = acc[mt][j][2];
            S[(r + 8) * 132 + cc + 1] = acc[mt][j][3];
        }
    __syncthreads();

    if (EPI == 0) {
        float* Cf = reinterpret_cast<float*>(Cout) + (long)z * sC;
        #pragma unroll
        for (int i = 0; i < 32; i++) {
            int idx = tid + i * NTHR;
            int r = idx >> 5, c4 = (idx & 31) * 4;
            float4 v;
            v.x = S[r * 132 + c4 + 0] * alpha;
            v.y = S[r * 132 + c4 + 1] * alpha;
            v.z = S[r * 132 + c4 + 2] * alpha;
            v.w = S[r * 132 + c4 + 3] * alpha;
            *reinterpret_cast<float4*>(Cf + (long)(m0 + r) * ldW + n0 + c4) = v;
        }
    } else if (EPI == 1) {
        fp16* Ch = reinterpret_cast<fp16*>(Cout) + (long)z * sC;
        #pragma unroll
        for (int i = 0; i < 32; i++) {
            int idx = tid + i * NTHR;
            int r = idx >> 5, c4 = (idx & 31) * 4;
            float f0 = S[r * 132 + c4 + 0] * alpha;
            float f1 = S[r * 132 + c4 + 1] * alpha;
            float f2 = S[r * 132 + c4 + 2] * alpha;
            float f3 = S[r * 132 + c4 + 3] * alpha;
            if (bias) {
                f0 += bias[n0 + c4 + 0];
                f1 += bias[n0 + c4 + 1];
                f2 += bias[n0 + c4 + 2];
                f3 += bias[n0 + c4 + 3];
            }
            uint2 w;
            w.x = pack2h(f0, f1);
            w.y = pack2h(f2, f3);
            *reinterpret_cast<uint2*>(Ch + (long)(m0 + r) * ldW + n0 + c4) = w;
        }
    } else {  // EPI 3: transposed fp16
        fp16* Ch = reinterpret_cast<fp16*>(Cout) + (long)z * sC;
        const long colbase = (long)z * colPerZ + m0;
        #pragma unroll
        for (int i = 0; i < 64; i++) {
            int idx = tid + i * NTHR;
            int n = idx >> 6, m = (idx & 63) * 2;
            float bb = bias ? bias[n0 + n] : 0.0f;
            float f0 = S[m * 132 + n] * alpha + bb;
            float f1 = S[(m + 1) * 132 + n] * alpha + bb;
            *reinterpret_cast<uint32_t*>(Ch + (long)(n0 + n) * ldW + colbase + m) = pack2h(f0, f1);
        }
    }
}

// ---------------- softmax over fp16 scores, in place ----------------
__global__ __launch_bounds__(256)
void softmax_h(fp16* __restrict__ att)
{
    const int row = blockIdx.x;                    // 0..NH*NT-1
    fp16* p = att + (size_t)row * NT;
    const int tid = threadIdx.x, lane = tid & 31, wid = tid >> 5;
    __shared__ float red[8];

    float v[8];
    {
        uint4 w = *reinterpret_cast<const uint4*>(p + tid * 8);
        __half2 h0 = *reinterpret_cast<__half2*>(&w.x);
        __half2 h1 = *reinterpret_cast<__half2*>(&w.y);
        __half2 h2 = *reinterpret_cast<__half2*>(&w.z);
        __half2 h3 = *reinterpret_cast<__half2*>(&w.w);
        v[0] = __half2float(h0.x); v[1] = __half2float(h0.y);
        v[2] = __half2float(h1.x); v[3] = __half2float(h1.y);
        v[4] = __half2float(h2.x); v[5] = __half2float(h2.y);
        v[6] = __half2float(h3.x); v[7] = __half2float(h3.y);
    }
    float mx = v[0];
    #pragma unroll
    for (int i = 1; i < 8; i++) mx = fmaxf(mx, v[i]);
    #pragma unroll
    for (int s = 16; s > 0; s >>= 1) mx = fmaxf(mx, __shfl_xor_sync(~0u, mx, s));
    if (lane == 0) red[wid] = mx;
    __syncthreads();
    {
        float m = red[lane & 7];
        #pragma unroll
        for (int s = 4; s > 0; s >>= 1) m = fmaxf(m, __shfl_xor_sync(~0u, m, s));
        mx = __shfl_sync(~0u, m, 0);
    }

    float sum = 0.0f;
    #pragma unroll
    for (int i = 0; i < 8; i++) { v[i] = __expf(v[i] - mx); sum += v[i]; }
    #pragma unroll
    for (int s = 16; s > 0; s >>= 1) sum += __shfl_xor_sync(~0u, sum, s);
    __syncthreads();          // protect red[] reuse
    if (lane == 0) red[wid] = sum;
    __syncthreads();
    {
        float t = red[lane & 7];
        #pragma unroll
        for (int s = 4; s > 0; s >>= 1) t += __shfl_xor_sync(~0u, t, s);
        sum = __shfl_sync(~0u, t, 0);
    }
    const float inv = 1.0f / sum;

    uint4 w;
    w.x = pack2h(v[0] * inv, v[1] * inv);
    w.y = pack2h(v[2] * inv, v[3] * inv);
    w.z = pack2h(v[4] * inv, v[5] * inv);
    w.w = pack2h(v[6] * inv, v[7] * inv);
    *reinterpret_cast<uint4*>(p + tid * 8) = w;
}

// ---------------- split-K reduce + bias + residual + LayerNorm ----------------
__global__ __launch_bounds__(128)
void reduce_ln_kernel(const float* __restrict__ parts, const float* __restrict__ zres,
                      const float* __restrict__ bfv, float* __restrict__ out)
{
    const int row = blockIdx.x;
    const int tid = threadIdx.x, lane = tid & 31, wid = tid >> 5;
    float4 acc = reinterpret_cast<const float4*>(zres + (size_t)row * NE)[tid];
    const float b = bfv[row];
    acc.x += b; acc.y += b; acc.z += b; acc.w += b;
    #pragma unroll
    for (int p = 0; p < SPLITK; p++) {
        float4 t = reinterpret_cast<const float4*>(
            parts + (size_t)p * NT * NE + (size_t)row * NE)[tid];
        acc.x += t.x; acc.y += t.y; acc.z += t.z; acc.w += t.w;
    }

    __shared__ float red[4];
    float s = acc.x + acc.y + acc.z + acc.w;
    #pragma unroll
    for (int q = 16; q > 0; q >>= 1) s += __shfl_xor_sync(~0u, s, q);
    if (lane == 0) red[wid] = s;
    __syncthreads();
    {
        float t = red[lane & 3];
        #pragma unroll
        for (int q = 2; q > 0; q >>= 1) t += __shfl_xor_sync(~0u, t, q);
        s = __shfl_sync(~0u, t, 0);
    }
    const float mean = s * (1.0f / NE);

    const float dx = acc.x - mean, dy = acc.y - mean, dz = acc.z - mean, dw = acc.w - mean;
    float s2 = dx * dx + dy * dy + dz * dz + dw * dw;
    #pragma unroll
    for (int q = 16; q > 0; q >>= 1) s2 += __shfl_xor_sync(~0u, s2, q);
    __syncthreads();
    if (lane == 0) red[wid] = s2;
    __syncthreads();
    {
        float t = red[lane & 3];
        #pragma unroll
        for (int q = 2; q > 0; q >>= 1) t += __shfl_xor_sync(~0u, t, q);
        s2 = __shfl_sync(~0u, t, 0);
    }
    const float rstd = rsqrtf(s2 * (1.0f / NE) + 1e-4f);

    float4 o;
    o.x = dx * rstd; o.y = dy * rstd; o.z = dz * rstd; o.w = dw * rstd;
    reinterpret_cast<float4*>(out + (size_t)row * NE)[tid] = o;
}

// ---------------- launch ----------------
static inline int cblocks(long nq) {
    long b = (nq + 1023) / 1024;
    if (b > 2048) b = 2048;
    if (b < 1) b = 1;
    return (int)b;
}

extern "C" void kernel_launch(void* const* d_in, const int* in_sizes, int n_in,
                              void* d_out, int out_size)
{
    const float* x  = (const float*)d_in[0];
    const float* y  = (const float*)d_in[1];
    const float* z  = (const float*)d_in[2];
    const float* Wq = (const float*)d_in[3];
    const float* bq = (const float*)d_in[4];
    const float* Wk = (const float*)d_in[5];
    const float* bk = (const float*)d_in[6];
    const float* Wv = (const float*)d_in[7];
    const float* bv = (const float*)d_in[8];
    const float* Wf = (const float*)d_in[9];
    const float* bf = (const float*)d_in[10];
    float* out = (float*)d_out;

    fp16 *xe, *ye, *ze, *Wqe, *Wke, *Wve, *Wfe, *q, *k, *v, *att, *hd;
    float *pt;
    cudaGetSymbolAddress((void**)&xe,  g_xe);
    cudaGetSymbolAddress((void**)&ye,  g_ye);
    cudaGetSymbolAddress((void**)&ze,  g_ze);
    cudaGetSymbolAddress((void**)&Wqe, g_Wqe);
    cudaGetSymbolAddress((void**)&Wke, g_Wke);
    cudaGetSymbolAddress((void**)&Wve, g_Wve);
    cudaGetSymbolAddress((void**)&Wfe, g_Wfe);
    cudaGetSymbolAddress((void**)&q,   g_q);
    cudaGetSymbolAddress((void**)&k,   g_k);
    cudaGetSymbolAddress((void**)&v,   g_v);
    cudaGetSymbolAddress((void**)&att, g_att);
    cudaGetSymbolAddress((void**)&hd,  g_hd);
    cudaGetSymbolAddress((void**)&pt,  g_part);

    cudaFuncSetAttribute(mma_gemm<0>, cudaFuncAttributeMaxDynamicSharedMemorySize, GEMM_SMEM);
    cudaFuncSetAttribute(mma_gemm<1>, cudaFuncAttributeMaxDynamicSharedMemorySize, GEMM_SMEM);
    cudaFuncSetAttribute(mma_gemm<3>, cudaFuncAttributeMaxDynamicSharedMemorySize, GEMM_SMEM);

    const float inv_sqrt_T = 1.0f / sqrtf((float)NT);

    // ---- casts (nq counts float4 groups) ----
    {
        dim3 g3(cblocks((long)NT * NE / 4), 3, 1);
        cast3_kernel<<<g3, 256>>>(x, xe, y, ye, z, ze, (long)NT * NE / 4);
        dim3 gW(cblocks((long)NH * NE * NE / 4), 3, 1);
        cast3_kernel<<<gW, 256>>>(Wq, Wqe, Wk, Wke, Wv, Wve, (long)NH * NE * NE / 4);
        cast_kernel<<<cblocks((long)NT * NHT / 4), 256>>>(Wf, Wfe, (long)NT * NHT / 4);
    }

    // ---- QKV projections (batched over heads) ----
    dim3 gP(NE / BN, NT / BM, NH);
    mma_gemm<1><<<gP, NTHR, GEMM_SMEM>>>(xe, Wqe, q, NE, NE, NE, NE,
                                         0, (long)NE * NE, (long)NT * NE, 0,
                                         1.0f, bq, NE);
    mma_gemm<1><<<gP, NTHR, GEMM_SMEM>>>(ye, Wke, k, NE, NE, NE, NE,
                                         0, (long)NE * NE, (long)NT * NE, 0,
                                         1.0f, bk, NE);
    mma_gemm<3><<<gP, NTHR, GEMM_SMEM>>>(ze, Wve, v, NE, NE, NE, NT,
                                         0, (long)NE * NE, (long)NE * NT, 0,
                                         1.0f, bv, NE);

    // ---- scores -> fp16 (1/sqrt(T) folded into alpha), into att buffer ----
    dim3 gS(NT / BN, NT / BM, NH);
    mma_gemm<1><<<gS, NTHR, GEMM_SMEM>>>(q, k, att, NE, NE, NE, NT,
                                         (long)NT * NE, (long)NT * NE, (long)NT * NT, 0,
                                         inv_sqrt_T, nullptr, 0);

    // ---- softmax in place on fp16 ----
    softmax_h<<<NH * NT, 256>>>(att);

    // ---- heads = att @ v -> transposed concat [E, HT] ----
    dim3 gAV(NE / BN, NT / BM, NH);
    mma_gemm<3><<<gAV, NTHR, GEMM_SMEM>>>(att, v, hd, NT, NT, NT, NHT,
                                          (long)NT * NT, (long)NE * NT, 0, NT,
                                          1.0f, nullptr, 0);

    // ---- final linear, split-K = 8 ----
    dim3 gF(NE / BN, NT / BM, SPLITK);
    mma_gemm<0><<<gF, NTHR, GEMM_SMEM>>>(Wfe, hd, pt, KSPLIT, NHT, NHT, NE,
                                         KSPLIT, KSPLIT, (long)NT * NE, 0,
                                         1.0f, nullptr, 0);

    // ---- reduce + bias + residual + LayerNorm ----
    reduce_ln_kernel<<<NT, 128>>>(pt, z, bf, out);
}

// round 16
// speedup vs baseline: 1.3926x; 1.3926x over previous
#include <cuda_runtime.h>
#include <cuda_fp16.h>
#include <math.h>
#include <stdint.h>

#define NH 8
#define NT 2048
#define NE 512
#define NHT (NH * NT)
#define SPLITK 8
#define KSPLIT (NHT / SPLITK)

typedef __half fp16;

// ---------------- scratch (device globals; no allocation anywhere) ----------------
__device__ __align__(256) fp16 g_xe[(size_t)NT * NE];
__device__ __align__(256) fp16 g_ye[(size_t)NT * NE];
__device__ __align__(256) fp16 g_ze[(size_t)NT * NE];
__device__ __align__(256) fp16 g_Wqe[(size_t)NH * NE * NE];
__device__ __align__(256) fp16 g_Wke[(size_t)NH * NE * NE];
__device__ __align__(256) fp16 g_Wve[(size_t)NH * NE * NE];
__device__ __align__(256) fp16 g_Wfe[(size_t)NT * NHT];
__device__ __align__(256) fp16 g_q[(size_t)NH * NT * NE];    // [h][t][e]
__device__ __align__(256) fp16 g_k[(size_t)NH * NT * NE];    // [h][t][e]
__device__ __align__(256) fp16 g_v[(size_t)NH * NE * NT];    // [h][e][t]  (transposed)
__device__ __align__(256) fp16 g_att[(size_t)NH * NT * NT];  // scores then att (in-place)
__device__ __align__(256) fp16 g_hd[(size_t)NE * NHT];       // heads^T == concat^T [e][h*t]
__device__ __align__(256) float g_part[(size_t)SPLITK * NT * NE];

// ---------------- helpers ----------------
__device__ __forceinline__ uint32_t smem_u32(const void* p) {
    uint32_t a;
    asm("{ .reg .u64 t; cvta.to.shared.u64 t, %1; cvt.u32.u64 %0, t; }" : "=r"(a) : "l"(p));
    return a;
}
__device__ __forceinline__ void cp_async16(uint32_t dst, const void* src) {
    asm volatile("cp.async.cg.shared.global [%0], [%1], 16;" :: "r"(dst), "l"(src));
}
#define CP_COMMIT() asm volatile("cp.async.commit_group;")
#define CP_WAIT1()  asm volatile("cp.async.wait_group 1;")

__device__ __forceinline__ void ldm_x4(uint32_t* r, uint32_t addr) {
    asm volatile("ldmatrix.sync.aligned.m8n8.x4.shared.b16 {%0,%1,%2,%3}, [%4];"
                 : "=r"(r[0]), "=r"(r[1]), "=r"(r[2]), "=r"(r[3]) : "r"(addr));
}
__device__ __forceinline__ void mma16816(float* c, const uint32_t* a, const uint32_t* b) {
    asm volatile(
        "mma.sync.aligned.m16n8k16.row.col.f32.f16.f16.f32 "
        "{%0,%1,%2,%3}, {%4,%5,%6,%7}, {%8,%9}, {%0,%1,%2,%3};"
        : "+f"(c[0]), "+f"(c[1]), "+f"(c[2]), "+f"(c[3])
        : "r"(a[0]), "r"(a[1]), "r"(a[2]), "r"(a[3]), "r"(b[0]), "r"(b[1]));
}
__device__ __forceinline__ uint32_t pack2h(float a, float b) {
    __half2 h = __floats2half2_rn(a, b);
    return *reinterpret_cast<uint32_t*>(&h);
}

// ---------------- fp32 -> fp16 cast (3 tensors per launch) ----------------
__global__ __launch_bounds__(256)
void cast3_kernel(const float* __restrict__ s0, fp16* __restrict__ d0,
                  const float* __restrict__ s1, fp16* __restrict__ d1,
                  const float* __restrict__ s2, fp16* __restrict__ d2, long nq)
{
    const float* src = (blockIdx.y == 0) ? s0 : (blockIdx.y == 1) ? s1 : s2;
    fp16*       dst = (blockIdx.y == 0) ? d0 : (blockIdx.y == 1) ? d1 : d2;
    long i = (long)blockIdx.x * blockDim.x + threadIdx.x;
    const long stride = (long)gridDim.x * blockDim.x;
    for (; i < nq; i += stride) {
        float4 f = reinterpret_cast<const float4*>(src)[i];
        uint2 w;
        w.x = pack2h(f.x, f.y);
        w.y = pack2h(f.z, f.w);
        reinterpret_cast<uint2*>(dst)[i] = w;
    }
}

__global__ __launch_bounds__(256)
void cast_kernel(const float* __restrict__ src, fp16* __restrict__ dst, long nq)
{
    long i = (long)blockIdx.x * blockDim.x + threadIdx.x;
    const long stride = (long)gridDim.x * blockDim.x;
    for (; i < nq; i += stride) {
        float4 f = reinterpret_cast<const float4*>(src)[i];
        uint2 w;
        w.x = pack2h(f.x, f.y);
        w.y = pack2h(f.z, f.w);
        reinterpret_cast<uint2*>(dst)[i] = w;
    }
}

// ---------------- GEMM tile config (R10 shape: 8 warps, warp tile 32x64) --------
#define BM 128
#define BN 128
#define BKE 64
#define STAGES 3
#define STAGE_BYTES (BM * BKE * 2 + BN * BKE * 2)   // 32768
#define GEMM_SMEM (STAGES * STAGE_BYTES)            // 98304 (x2 CTAs = 196K)

// Mainloop body shared by both GEMM kernels (B-fragment double-buffered).
#define GEMM_MAINLOOP(ACC)                                                        \
    prefetch(0, 0); CP_COMMIT();                                                  \
    prefetch(1, 1); CP_COMMIT();                                                  \
    const int a_r  = lane & 15;                                                   \
    const int a_kc = lane >> 4;                                                   \
    const int b_r  = (lane & 7) + ((lane >> 4) << 3);                             \
    const int b_kc = (lane >> 3) & 1;                                             \
    for (int ch = 0; ch < NCH; ch++) {                                            \
        CP_WAIT1();                                                               \
        __syncthreads();                                                          \
        if (ch + 2 < NCH) prefetch((ch + 2) % STAGES, ch + 2);                    \
        CP_COMMIT();                                                              \
        const int s = ch % STAGES;                                                \
        _Pragma("unroll")                                                         \
        for (int ks = 0; ks < 4; ks++) {                                          \
            uint32_t a[2][4];                                                     \
            _Pragma("unroll")                                                     \
            for (int mt = 0; mt < 2; mt++) {                                      \
                int r = wm * 32 + mt * 16 + a_r;                                  \
                ldm_x4(a[mt], aAddr(s, r, 2 * ks + a_kc));                        \
            }                                                                     \
            uint32_t b[2][4];                                                     \
            {                                                                     \
                int r = wn * 64 + b_r;                                            \
                ldm_x4(b[0], bAddr(s, r, 2 * ks + b_kc));                         \
            }                                                                     \
            _Pragma("unroll")                                                     \
            for (int g = 0; g < 4; g++) {                                         \
                const int cur = g & 1;                                            \
                if (g < 3) {                                                      \
                    int r = wn * 64 + (g + 1) * 16 + b_r;                         \
                    ldm_x4(b[cur ^ 1], bAddr(s, r, 2 * ks + b_kc));               \
                }                                                                 \
                _Pragma("unroll")                                                 \
                for (int mt = 0; mt < 2; mt++) {                                  \
                    mma16816(ACC[mt][2 * g],     a[mt], &b[cur][0]);              \
                    mma16816(ACC[mt][2 * g + 1], a[mt], &b[cur][2]);              \
                }                                                                 \
            }                                                                     \
        }                                                                         \
    }

// ---------------- generic mma.sync fp16 GEMM (2 CTAs/SM) ----------------
// EPI 0: fp32 out (alpha)
// EPI 1: fp16 out in-row (alpha, +bias_n)
// EPI 3: fp16 out transposed (+bias_n)   d[(n0+n)*ldW + z*colPerZ + m0+m]
template <int EPI>
__global__ __launch_bounds__(256, 2)
void mma_gemm(const fp16* __restrict__ A, const fp16* __restrict__ B, void* Cout,
              int K, long lda, long ldb, long ldW,
              long sA, long sB, long sC, long colPerZ,
              float alpha, const float* __restrict__ bias, long sBias)
{
    extern __shared__ char smem[];
    const int tid = threadIdx.x, lane = tid & 31, wid = tid >> 5;
    const int wm = wid & 3, wn = wid >> 2;
    const int m0 = blockIdx.y * BM, n0 = blockIdx.x * BN, z = blockIdx.z;
    A += (long)z * sA;
    B += (long)z * sB;
    if (bias) bias += (long)z * sBias;
    const uint32_t sbase = smem_u32(smem);

    const int ldr  = tid >> 1;
    const int ldc0 = (tid & 1) * 4;
    const fp16* Ag = A + (long)(m0 + ldr) * lda + ldc0 * 8;
    const fp16* Bg = B + (long)(n0 + ldr) * ldb + ldc0 * 8;

    auto aAddr = [&](int s, int r, int c) -> uint32_t {
        return sbase + s * STAGE_BYTES + ((((uint32_t)r << 3) | (uint32_t)(c ^ (r & 7))) << 4);
    };
    auto bAddr = [&](int s, int r, int c) -> uint32_t {
        return sbase + s * STAGE_BYTES + BM * BKE * 2 +
               ((((uint32_t)r << 3) | (uint32_t)(c ^ (r & 7))) << 4);
    };
    auto prefetch = [&](int s, int ch) {
        const fp16* ap = Ag + (long)ch * BKE;
        const fp16* bp = Bg + (long)ch * BKE;
        #pragma unroll
        for (int c = 0; c < 4; c++) {
            cp_async16(aAddr(s, ldr, ldc0 + c), ap + c * 8);
            cp_async16(bAddr(s, ldr, ldc0 + c), bp + c * 8);
        }
    };

    float acc[2][8][4] = {};
    const int NCH = K / BKE;

    GEMM_MAINLOOP(acc)
    __syncthreads();

    // ---- bounce fragments to smem fp32 tile [128][132] ----
    float* S = reinterpret_cast<float*>(smem);
    #pragma unroll
    for (int mt = 0; mt < 2; mt++)
        #pragma unroll
        for (int j = 0; j < 8; j++) {
            int r  = wm * 32 + mt * 16 + (lane >> 2);
            int cc = wn * 64 + j * 8 + (lane & 3) * 2;
            S[r * 132 + cc]           = acc[mt][j][0];
            S[r * 132 + cc + 1]       = acc[mt][j][1];
            S[(r + 8) * 132 + cc]     = acc[mt][j][2];
            S[(r + 8) * 132 + cc + 1] = acc[mt][j][3];
        }
    __syncthreads();

    if (EPI == 0) {
        float* Cf = reinterpret_cast<float*>(Cout) + (long)z * sC;
        #pragma unroll
        for (int i = 0; i < 16; i++) {
            int idx = tid + i * 256;
            int r = idx >> 5, c4 = (idx & 31) * 4;
            float4 v;
            v.x = S[r * 132 + c4 + 0] * alpha;
            v.y = S[r * 132 + c4 + 1] * alpha;
            v.z = S[r * 132 + c4 + 2] * alpha;
            v.w = S[r * 132 + c4 + 3] * alpha;
            *reinterpret_cast<float4*>(Cf + (long)(m0 + r) * ldW + n0 + c4) = v;
        }
    } else if (EPI == 1) {
        fp16* Ch = reinterpret_cast<fp16*>(Cout) + (long)z * sC;
        #pragma unroll
        for (int i = 0; i < 16; i++) {
            int idx = tid + i * 256;
            int r = idx >> 5, c4 = (idx & 31) * 4;
            float f0 = S[r * 132 + c4 + 0] * alpha;
            float f1 = S[r * 132 + c4 + 1] * alpha;
            float f2 = S[r * 132 + c4 + 2] * alpha;
            float f3 = S[r * 132 + c4 + 3] * alpha;
            if (bias) {
                f0 += bias[n0 + c4 + 0];
                f1 += bias[n0 + c4 + 1];
                f2 += bias[n0 + c4 + 2];
                f3 += bias[n0 + c4 + 3];
            }
            uint2 w;
            w.x = pack2h(f0, f1);
            w.y = pack2h(f2, f3);
            *reinterpret_cast<uint2*>(Ch + (long)(m0 + r) * ldW + n0 + c4) = w;
        }
    } else {  // EPI 3: transposed fp16
        fp16* Ch = reinterpret_cast<fp16*>(Cout) + (long)z * sC;
        const long colbase = (long)z * colPerZ + m0;
        #pragma unroll
        for (int i = 0; i < 32; i++) {
            int idx = tid + i * 256;
            int n = idx >> 6, m = (idx & 63) * 2;
            float bb = bias ? bias[n0 + n] : 0.0f;
            float f0 = S[m * 132 + n] * alpha + bb;
            float f1 = S[(m + 1) * 132 + n] * alpha + bb;
            *reinterpret_cast<uint32_t*>(Ch + (long)(n0 + n) * ldW + colbase + m) = pack2h(f0, f1);
        }
    }
}

// ---------------- merged QKV projection GEMM ----------------
// z = op*8 + h; op 0: q rows, 1: k rows, 2: v transposed. M=NT, N=K=NE.
__global__ __launch_bounds__(256, 2)
void qkv_gemm(const fp16* __restrict__ xe, const fp16* __restrict__ ye,
              const fp16* __restrict__ ze,
              const fp16* __restrict__ Wq, const fp16* __restrict__ Wk,
              const fp16* __restrict__ Wv,
              fp16* __restrict__ qo, fp16* __restrict__ ko, fp16* __restrict__ vo,
              const float* __restrict__ bq, const float* __restrict__ bk,
              const float* __restrict__ bv)
{
    extern __shared__ char smem[];
    const int tid = threadIdx.x, lane = tid & 31, wid = tid >> 5;
    const int wm = wid & 3, wn = wid >> 2;
    const int m0 = blockIdx.y * BM, n0 = blockIdx.x * BN;
    const int op = blockIdx.z >> 3, h = blockIdx.z & 7;
    const fp16* A = (op == 0) ? xe : (op == 1) ? ye : ze;
    const fp16* B = ((op == 0) ? Wq : (op == 1) ? Wk : Wv) + (long)h * NE * NE;
    const float* bias = ((op == 0) ? bq : (op == 1) ? bk : bv) + (long)h * NE;
    const uint32_t sbase = smem_u32(smem);

    const int ldr  = tid >> 1;
    const int ldc0 = (tid & 1) * 4;
    const fp16* Ag = A + (long)(m0 + ldr) * NE + ldc0 * 8;
    const fp16* Bg = B + (long)(n0 + ldr) * NE + ldc0 * 8;

    auto aAddr = [&](int s, int r, int c) -> uint32_t {
        return sbase + s * STAGE_BYTES + ((((uint32_t)r << 3) | (uint32_t)(c ^ (r & 7))) << 4);
    };
    auto bAddr = [&](int s, int r, int c) -> uint32_t {
        return sbase + s * STAGE_BYTES + BM * BKE * 2 +
               ((((uint32_t)r << 3) | (uint32_t)(c ^ (r & 7))) << 4);
    };
    auto prefetch = [&](int s, int ch) {
        const fp16* ap = Ag + (long)ch * BKE;
        const fp16* bp = Bg + (long)ch * BKE;
        #pragma unroll
        for (int c = 0; c < 4; c++) {
            cp_async16(aAddr(s, ldr, ldc0 + c), ap + c * 8);
            cp_async16(bAddr(s, ldr, ldc0 + c), bp + c * 8);
        }
    };

    float acc[2][8][4] = {};
    const int NCH = NE / BKE;

    GEMM_MAINLOOP(acc)
    __syncthreads();

    float* S = reinterpret_cast<float*>(smem);
    #pragma unroll
    for (int mt = 0; mt < 2; mt++)
        #pragma unroll
        for (int j = 0; j < 8; j++) {
            int r  = wm * 32 + mt * 16 + (lane >> 2);
            int cc = wn * 64 + j * 8 + (lane & 3) * 2;
            S[r * 132 + cc]           = acc[mt][j][0];
            S[r * 132 + cc + 1]       = acc[mt][j][1];
            S[(r + 8) * 132 + cc]     = acc[mt][j][2];
            S[(r + 8) * 132 + cc + 1] = acc[mt][j][3];
        }
    __syncthreads();

    if (op < 2) {
        fp16* Ch = ((op == 0) ? qo : ko) + (long)h * NT * NE;
        #pragma unroll
        for (int i = 0; i < 16; i++) {
            int idx = tid + i * 256;
            int r = idx >> 5, c4 = (idx & 31) * 4;
            float f0 = S[r * 132 + c4 + 0] + bias[n0 + c4 + 0];
            float f1 = S[r * 132 + c4 + 1] + bias[n0 + c4 + 1];
            float f2 = S[r * 132 + c4 + 2] + bias[n0 + c4 + 2];
            float f3 = S[r * 132 + c4 + 3] + bias[n0 + c4 + 3];
            uint2 w;
            w.x = pack2h(f0, f1);
            w.y = pack2h(f2, f3);
            *reinterpret_cast<uint2*>(Ch + (long)(m0 + r) * NE + n0 + c4) = w;
        }
    } else {  // v: transposed [e][t]
        fp16* Ch = vo + (long)h * NE * NT;
        #pragma unroll
        for (int i = 0; i < 32; i++) {
            int idx = tid + i * 256;
            int n = idx >> 6, m = (idx & 63) * 2;
            float bb = bias[n0 + n];
            float f0 = S[m * 132 + n] + bb;
            float f1 = S[(m + 1) * 132 + n] + bb;
            *reinterpret_cast<uint32_t*>(Ch + (long)(n0 + n) * NT + m0 + m) = pack2h(f0, f1);
        }
    }
}

// ---------------- softmax over fp16 scores, in place ----------------
__global__ __launch_bounds__(256)
void softmax_h(fp16* __restrict__ att)
{
    const int row = blockIdx.x;
    fp16* p = att + (size_t)row * NT;
    const int tid = threadIdx.x, lane = tid & 31, wid = tid >> 5;
    __shared__ float red[8];

    float v[8];
    {
        uint4 w = *reinterpret_cast<const uint4*>(p + tid * 8);
        __half2 h0 = *reinterpret_cast<__half2*>(&w.x);
        __half2 h1 = *reinterpret_cast<__half2*>(&w.y);
        __half2 h2 = *reinterpret_cast<__half2*>(&w.z);
        __half2 h3 = *reinterpret_cast<__half2*>(&w.w);
        v[0] = __half2float(h0.x); v[1] = __half2float(h0.y);
        v[2] = __half2float(h1.x); v[3] = __half2float(h1.y);
        v[4] = __half2float(h2.x); v[5] = __half2float(h2.y);
        v[6] = __half2float(h3.x); v[7] = __half2float(h3.y);
    }
    float mx = v[0];
    #pragma unroll
    for (int i = 1; i < 8; i++) mx = fmaxf(mx, v[i]);
    #pragma unroll
    for (int s = 16; s > 0; s >>= 1) mx = fmaxf(mx, __shfl_xor_sync(~0u, mx, s));
    if (lane == 0) red[wid] = mx;
    __syncthreads();
    {
        float m = red[lane & 7];
        #pragma unroll
        for (int s = 4; s > 0; s >>= 1) m = fmaxf(m, __shfl_xor_sync(~0u, m, s));
        mx = __shfl_sync(~0u, m, 0);
    }

    float sum = 0.0f;
    #pragma unroll
    for (int i = 0; i < 8; i++) { v[i] = __expf(v[i] - mx); sum += v[i]; }
    #pragma unroll
    for (int s = 16; s > 0; s >>= 1) sum += __shfl_xor_sync(~0u, sum, s);
    __syncthreads();
    if (lane == 0) red[wid] = sum;
    __syncthreads();
    {
        float t = red[lane & 7];
        #pragma unroll
        for (int s = 4; s > 0; s >>= 1) t += __shfl_xor_sync(~0u, t, s);
        sum = __shfl_sync(~0u, t, 0);
    }
    const float inv = 1.0f / sum;

    uint4 w;
    w.x = pack2h(v[0] * inv, v[1] * inv);
    w.y = pack2h(v[2] * inv, v[3] * inv);
    w.z = pack2h(v[4] * inv, v[5] * inv);
    w.w = pack2h(v[6] * inv, v[7] * inv);
    *reinterpret_cast<uint4*>(p + tid * 8) = w;
}

// ---------------- split-K reduce + bias + residual + LayerNorm ----------------
__global__ __launch_bounds__(128)
void reduce_ln_kernel(const float* __restrict__ parts, const float* __restrict__ zres,
                      const float* __restrict__ bfv, float* __restrict__ out)
{
    const int row = blockIdx.x;
    const int tid = threadIdx.x, lane = tid & 31, wid = tid >> 5;
    float4 acc = reinterpret_cast<const float4*>(zres + (size_t)row * NE)[tid];
    const float b = bfv[row];
    acc.x += b; acc.y += b; acc.z += b; acc.w += b;
    #pragma unroll
    for (int p = 0; p < SPLITK; p++) {
        float4 t = reinterpret_cast<const float4*>(
            parts + (size_t)p * NT * NE + (size_t)row * NE)[tid];
        acc.x += t.x; acc.y += t.y; acc.z += t.z; acc.w += t.w;
    }

    __shared__ float red[4];
    float s = acc.x + acc.y + acc.z + acc.w;
    #pragma unroll
    for (int q = 16; q > 0; q >>= 1) s += __shfl_xor_sync(~0u, s, q);
    if (lane == 0) red[wid] = s;
    __syncthreads();
    {
        float t = red[lane & 3];
        #pragma unroll
        for (int q = 2; q > 0; q >>= 1) t += __shfl_xor_sync(~0u, t, q);
        s = __shfl_sync(~0u, t, 0);
    }
    const float mean = s * (1.0f / NE);

    const float dx = acc.x - mean, dy = acc.y - mean, dz = acc.z - mean, dw = acc.w - mean;
    float s2 = dx * dx + dy * dy + dz * dz + dw * dw;
    #pragma unroll
    for (int q = 16; q > 0; q >>= 1) s2 += __shfl_xor_sync(~0u, s2, q);
    __syncthreads();
    if (lane == 0) red[wid] = s2;
    __syncthreads();
    {
        float t = red[lane & 3];
        #pragma unroll
        for (int q = 2; q > 0; q >>= 1) t += __shfl_xor_sync(~0u, t, q);
        s2 = __shfl_sync(~0u, t, 0);
    }
    const float rstd = rsqrtf(s2 * (1.0f / NE) + 1e-4f);

    float4 o;
    o.x = dx * rstd; o.y = dy * rstd; o.z = dz * rstd; o.w = dw * rstd;
    reinterpret_cast<float4*>(out + (size_t)row * NE)[tid] = o;
}

// ---------------- launch ----------------
static inline int cblocks(long nq) {
    long b = (nq + 1023) / 1024;
    if (b > 2048) b = 2048;
    if (b < 1) b = 1;
    return (int)b;
}

extern "C" void kernel_launch(void* const* d_in, const int* in_sizes, int n_in,
                              void* d_out, int out_size)
{
    const float* x  = (const float*)d_in[0];
    const float* y  = (const float*)d_in[1];
    const float* z  = (const float*)d_in[2];
    const float* Wq = (const float*)d_in[3];
    const float* bq = (const float*)d_in[4];
    const float* Wk = (const float*)d_in[5];
    const float* bk = (const float*)d_in[6];
    const float* Wv = (const float*)d_in[7];
    const float* bv = (const float*)d_in[8];
    const float* Wf = (const float*)d_in[9];
    const float* bf = (const float*)d_in[10];
    float* out = (float*)d_out;

    fp16 *xe, *ye, *ze, *Wqe, *Wke, *Wve, *Wfe, *q, *k, *v, *att, *hd;
    float *pt;
    cudaGetSymbolAddress((void**)&xe,  g_xe);
    cudaGetSymbolAddress((void**)&ye,  g_ye);
    cudaGetSymbolAddress((void**)&ze,  g_ze);
    cudaGetSymbolAddress((void**)&Wqe, g_Wqe);
    cudaGetSymbolAddress((void**)&Wke, g_Wke);
    cudaGetSymbolAddress((void**)&Wve, g_Wve);
    cudaGetSymbolAddress((void**)&Wfe, g_Wfe);
    cudaGetSymbolAddress((void**)&q,   g_q);
    cudaGetSymbolAddress((void**)&k,   g_k);
    cudaGetSymbolAddress((void**)&v,   g_v);
    cudaGetSymbolAddress((void**)&att, g_att);
    cudaGetSymbolAddress((void**)&hd,  g_hd);
    cudaGetSymbolAddress((void**)&pt,  g_part);

    cudaFuncSetAttribute(mma_gemm<0>, cudaFuncAttributeMaxDynamicSharedMemorySize, GEMM_SMEM);
    cudaFuncSetAttribute(mma_gemm<1>, cudaFuncAttributeMaxDynamicSharedMemorySize, GEMM_SMEM);
    cudaFuncSetAttribute(mma_gemm<3>, cudaFuncAttributeMaxDynamicSharedMemorySize, GEMM_SMEM);
    cudaFuncSetAttribute(qkv_gemm,   cudaFuncAttributeMaxDynamicSharedMemorySize, GEMM_SMEM);

    const float inv_sqrt_T = 1.0f / sqrtf((float)NT);

    // ---- casts (nq counts float4 groups) ----
    {
        dim3 g3(cblocks((long)NT * NE / 4), 3, 1);
        cast3_kernel<<<g3, 256>>>(x, xe, y, ye, z, ze, (long)NT * NE / 4);
        dim3 gW(cblocks((long)NH * NE * NE / 4), 3, 1);
        cast3_kernel<<<gW, 256>>>(Wq, Wqe, Wk, Wke, Wv, Wve, (long)NH * NE * NE / 4);
        cast_kernel<<<cblocks((long)NT * NHT / 4), 256>>>(Wf, Wfe, (long)NT * NHT / 4);
    }

    // ---- merged QKV projections (z = op*8 + h) ----
    dim3 gQKV(NE / BN, NT / BM, 3 * NH);
    qkv_gemm<<<gQKV, 256, GEMM_SMEM>>>(xe, ye, ze, Wqe, Wke, Wve, q, k, v, bq, bk, bv);

    // ---- scores -> fp16 (1/sqrt(T) folded into alpha), into att buffer ----
    dim3 gS(NT / BN, NT / BM, NH);
    mma_gemm<1><<<gS, 256, GEMM_SMEM>>>(q, k, att, NE, NE, NE, NT,
                                        (long)NT * NE, (long)NT * NE, (long)NT * NT, 0,
                                        inv_sqrt_T, nullptr, 0);

    // ---- softmax in place on fp16 ----
    softmax_h<<<NH * NT, 256>>>(att);

    // ---- heads = att @ v -> transposed concat [E, HT] ----
    dim3 gAV(NE / BN, NT / BM, NH);
    mma_gemm<3><<<gAV, 256, GEMM_SMEM>>>(att, v, hd, NT, NT, NT, NHT,
                                         (long)NT * NT, (long)NE * NT, 0, NT,
                                         1.0f, nullptr, 0);

    // ---- final linear, split-K = 8 ----
    dim3 gF(NE / BN, NT / BM, SPLITK);
    mma_gemm<0><<<gF, 256, GEMM_SMEM>>>(Wfe, hd, pt, KSPLIT, NHT, NHT, NE,
                                        KSPLIT, KSPLIT, (long)NT * NE, 0,
                                        1.0f, nullptr, 0);

    // ---- reduce + bias + residual + LayerNorm ----
    reduce_ln_kernel<<<NT, 128>>>(pt, z, bf, out);
}